// round 7
// baseline (speedup 1.0000x reference)
#include <cuda_runtime.h>
#include <stdint.h>

// MessagePassing: out[dst[e]] += x[src[e]], N=100000, E=1600000, D=32 fp32.
// edge_index int32 [2, E]: row 0 = src, row 1 = dst.
//
// Binning pipeline (counting sort by dst, fixed capacity, no prefix scan):
//   A) memsetAsync out + counts
//   B) 8 edges/thread: p = atomicAdd(counts[d]); bins[d*32+p] = s
//      (8 independent atomic chains in flight; RED fallback on overflow)
//   C) 8 lanes/node: gather binned rows, MLP=8, TREE-structured adds
//      (depth-4 instead of a 32-FADD serial chain), one 128B store.

#define D_FEAT    32
#define CHUNKS    8
#define MAX_NODES 100000
#define BIN_CAP   32       // Poisson(16); ~20 nodes overflow -> RED fallback

__device__ int g_counts[MAX_NODES];
__device__ int g_bins[(long)MAX_NODES * BIN_CAP];

__device__ __forceinline__ void red_add_v4(float* p, float4 v) {
    asm volatile("red.global.add.v4.f32 [%0], {%1, %2, %3, %4};"
                 :: "l"(p), "f"(v.x), "f"(v.y), "f"(v.z), "f"(v.w)
                 : "memory");
}

__device__ __forceinline__ float4 f4add(float4 a, float4 b) {
    return make_float4(a.x + b.x, a.y + b.y, a.z + b.z, a.w + b.w);
}

__device__ __forceinline__ void bin_one(int s, int d, const float4* x, float* out) {
    int p = atomicAdd(&g_counts[d], 1);
    if (p < BIN_CAP) {
        g_bins[(long)d * BIN_CAP + p] = s;
    } else {
        #pragma unroll
        for (int c = 0; c < CHUNKS; ++c)
            red_add_v4(out + (long)d * D_FEAT + c * 4,
                       __ldg(&x[(long)s * CHUNKS + c]));
    }
}

// Phase B: bin edges by dst, 8 edges per thread (8 atomic chains in flight).
__global__ void mp_bin_kernel(const float4* __restrict__ x,
                              const int* __restrict__ src,
                              const int* __restrict__ dst,
                              float* __restrict__ out,
                              long n_edges) {
    long t  = (long)blockIdx.x * blockDim.x + threadIdx.x;
    long e0 = t * 8;
    if (e0 >= n_edges) return;

    if (e0 + 8 <= n_edges) {
        int4 sa = __ldg((const int4*)(src + e0));
        int4 sb = __ldg((const int4*)(src + e0 + 4));
        int4 da = __ldg((const int4*)(dst + e0));
        int4 db = __ldg((const int4*)(dst + e0 + 4));
        bin_one(sa.x, da.x, x, out);
        bin_one(sa.y, da.y, x, out);
        bin_one(sa.z, da.z, x, out);
        bin_one(sa.w, da.w, x, out);
        bin_one(sb.x, db.x, x, out);
        bin_one(sb.y, db.y, x, out);
        bin_one(sb.z, db.z, x, out);
        bin_one(sb.w, db.w, x, out);
    } else {
        for (long e = e0; e < n_edges; ++e)
            bin_one(__ldg(&src[e]), __ldg(&dst[e]), x, out);
    }
}

// Phase C: 8 lanes per node; lane c owns 16B chunk c.
__global__ void mp_gather_kernel(const float4* __restrict__ x,
                                 float4* __restrict__ out,
                                 int n_nodes) {
    long t = (long)blockIdx.x * blockDim.x + threadIdx.x;
    int n = (int)(t >> 3);
    int c = (int)(t & 7);
    if (n >= n_nodes) return;

    int k = __ldg(&g_counts[n]);
    if (k > BIN_CAP) k = BIN_CAP;

    long op = (long)n * CHUNKS + c;
    float4 seed = out[op];   // RED-fallback contributions (normally 0)
    float4 acc = make_float4(0.f, 0.f, 0.f, 0.f);

    const int* brow = g_bins + (long)n * BIN_CAP;
    int j = 0;
    for (; j + 8 <= k; j += 8) {
        int4 sa = __ldg((const int4*)(brow + j));
        int4 sb = __ldg((const int4*)(brow + j + 4));
        float4 a0 = __ldg(&x[(long)sa.x * CHUNKS + c]);
        float4 a1 = __ldg(&x[(long)sa.y * CHUNKS + c]);
        float4 a2 = __ldg(&x[(long)sa.z * CHUNKS + c]);
        float4 a3 = __ldg(&x[(long)sa.w * CHUNKS + c]);
        float4 a4 = __ldg(&x[(long)sb.x * CHUNKS + c]);
        float4 a5 = __ldg(&x[(long)sb.y * CHUNKS + c]);
        float4 a6 = __ldg(&x[(long)sb.z * CHUNKS + c]);
        float4 a7 = __ldg(&x[(long)sb.w * CHUNKS + c]);
        // Tree reduction: depth 3 + 1 into acc (vs 32-FADD serial chain).
        float4 s01 = f4add(a0, a1);
        float4 s23 = f4add(a2, a3);
        float4 s45 = f4add(a4, a5);
        float4 s67 = f4add(a6, a7);
        float4 s03 = f4add(s01, s23);
        float4 s47 = f4add(s45, s67);
        acc = f4add(acc, f4add(s03, s47));
    }
    if (j + 4 <= k) {
        int4 sa = __ldg((const int4*)(brow + j));
        float4 a0 = __ldg(&x[(long)sa.x * CHUNKS + c]);
        float4 a1 = __ldg(&x[(long)sa.y * CHUNKS + c]);
        float4 a2 = __ldg(&x[(long)sa.z * CHUNKS + c]);
        float4 a3 = __ldg(&x[(long)sa.w * CHUNKS + c]);
        acc = f4add(acc, f4add(f4add(a0, a1), f4add(a2, a3)));
        j += 4;
    }
    for (; j < k; ++j) {
        int s = __ldg(&brow[j]);
        acc = f4add(acc, __ldg(&x[(long)s * CHUNKS + c]));
    }
    out[op] = f4add(acc, seed);
}

// Safety path (shape mismatch): edge-centric RED kernel.
__global__ void mp_scatter_kernel(const float4* __restrict__ x,
                                  const int* __restrict__ src,
                                  const int* __restrict__ dst,
                                  float* __restrict__ out,
                                  long n_edges) {
    long t = (long)blockIdx.x * blockDim.x + threadIdx.x;
    long e = t >> 3;
    int  c = (int)(t & 7);
    if (e >= n_edges) return;
    int s = __ldg(&src[e]);
    int d = __ldg(&dst[e]);
    float4 v = __ldg(&x[(long)s * CHUNKS + c]);
    red_add_v4(out + (long)d * D_FEAT + c * 4, v);
}

extern "C" void kernel_launch(void* const* d_in, const int* in_sizes, int n_in,
                              void* d_out, int out_size) {
    const float4* x   = (const float4*)d_in[0];
    const int*    ei  = (const int*)d_in[1];
    long n_edges = (long)in_sizes[1] / 2;
    const int* src = ei;
    const int* dst = ei + n_edges;
    float* out = (float*)d_out;
    int n_nodes = in_sizes[0] / D_FEAT;
    int threads = 256;

    cudaMemsetAsync(d_out, 0, (size_t)out_size * sizeof(float), 0);

    if (n_nodes > MAX_NODES) {
        long total = n_edges * CHUNKS;
        long blocks = (total + threads - 1) / threads;
        mp_scatter_kernel<<<(unsigned)blocks, threads>>>(x, src, dst, out, n_edges);
        return;
    }

    void* counts_ptr = nullptr;
    cudaGetSymbolAddress(&counts_ptr, g_counts);
    cudaMemsetAsync(counts_ptr, 0, (size_t)n_nodes * sizeof(int), 0);

    // Phase B: 8 edges/thread.
    {
        long groups = (n_edges + 7) / 8;
        long blocks = (groups + threads - 1) / threads;
        mp_bin_kernel<<<(unsigned)blocks, threads>>>(x, src, dst, out, n_edges);
    }
    // Phase C.
    {
        long total = (long)n_nodes * 8;
        long blocks = (total + threads - 1) / threads;
        mp_gather_kernel<<<(unsigned)blocks, threads>>>(x, (float4*)out, n_nodes);
    }
}

// round 8
// speedup vs baseline: 1.2947x; 1.2947x over previous
#include <cuda_runtime.h>
#include <stdint.h>

// MessagePassing: out[dst[e]] += x[src[e]], N=100000, E=1600000, D=32 fp32.
// edge_index int32 [2, E]: row 0 = src, row 1 = dst.
//
// Edge-centric scatter (measured at the LTS cap: ~423MB L2 traffic ~= 37us):
// 8 lanes per edge-group cover one 128B feature row (float4/lane); each group
// processes 8 edges with int4-vectorized index loads and all 8 gathers issued
// before any RED (MLP=8). Scatter via red.global.add.v4.f32 (fire-and-forget
// RED.128). Output zeroed via cudaMemsetAsync (graph-capturable memset node).

#define D_FEAT 32
#define CHUNKS 8   // D_FEAT / 4
#define EPT    8   // edges per thread-group

__device__ __forceinline__ void red_add_v4(float* p, float4 v) {
    asm volatile("red.global.add.v4.f32 [%0], {%1, %2, %3, %4};"
                 :: "l"(p), "f"(v.x), "f"(v.y), "f"(v.z), "f"(v.w)
                 : "memory");
}

__global__ void mp_scatter_kernel(const float4* __restrict__ x,
                                  const int* __restrict__ src,
                                  const int* __restrict__ dst,
                                  float* __restrict__ out,
                                  long n_edges) {
    long t = (long)blockIdx.x * blockDim.x + threadIdx.x;
    long g = t >> 3;          // edge-group index
    int  c = (int)(t & 7);    // 16B chunk within the 128B feature row
    long e0 = g * EPT;
    if (e0 >= n_edges) return;

    if (e0 + EPT <= n_edges) {
        // Vectorized index loads: e0 is a multiple of 8 -> 16B aligned.
        int4 sa = __ldg((const int4*)(src + e0));
        int4 sb = __ldg((const int4*)(src + e0 + 4));
        int4 da = __ldg((const int4*)(dst + e0));
        int4 db = __ldg((const int4*)(dst + e0 + 4));

        // Batch all 8 gathers (MLP=8) before any RED.
        float4 v0 = __ldg(&x[(long)sa.x * CHUNKS + c]);
        float4 v1 = __ldg(&x[(long)sa.y * CHUNKS + c]);
        float4 v2 = __ldg(&x[(long)sa.z * CHUNKS + c]);
        float4 v3 = __ldg(&x[(long)sa.w * CHUNKS + c]);
        float4 v4 = __ldg(&x[(long)sb.x * CHUNKS + c]);
        float4 v5 = __ldg(&x[(long)sb.y * CHUNKS + c]);
        float4 v6 = __ldg(&x[(long)sb.z * CHUNKS + c]);
        float4 v7 = __ldg(&x[(long)sb.w * CHUNKS + c]);

        int co = c * 4;
        red_add_v4(out + (long)da.x * D_FEAT + co, v0);
        red_add_v4(out + (long)da.y * D_FEAT + co, v1);
        red_add_v4(out + (long)da.z * D_FEAT + co, v2);
        red_add_v4(out + (long)da.w * D_FEAT + co, v3);
        red_add_v4(out + (long)db.x * D_FEAT + co, v4);
        red_add_v4(out + (long)db.y * D_FEAT + co, v5);
        red_add_v4(out + (long)db.z * D_FEAT + co, v6);
        red_add_v4(out + (long)db.w * D_FEAT + co, v7);
    } else {
        // Tail: scalar loop over remaining edges (not taken for E=1.6M).
        for (long e = e0; e < n_edges; ++e) {
            int s = __ldg(&src[e]);
            int d = __ldg(&dst[e]);
            float4 v = __ldg(&x[(long)s * CHUNKS + c]);
            red_add_v4(out + (long)d * D_FEAT + c * 4, v);
        }
    }
}

extern "C" void kernel_launch(void* const* d_in, const int* in_sizes, int n_in,
                              void* d_out, int out_size) {
    const float4* x   = (const float4*)d_in[0];
    const int*    ei  = (const int*)d_in[1];
    long n_edges = (long)in_sizes[1] / 2;      // edge_index has 2*E elements
    const int* src = ei;                       // row 0
    const int* dst = ei + n_edges;             // row 1
    float* out = (float*)d_out;

    // Zero the (poisoned) output via a memset node (faster than a kernel).
    cudaMemsetAsync(d_out, 0, (size_t)out_size * sizeof(float), 0);

    // Scatter-add: 8 lanes per edge-group, 8 edges per group.
    long groups = (n_edges + EPT - 1) / EPT;
    long total  = groups * 8;
    int threads = 256;
    long blocks = (total + threads - 1) / threads;
    mp_scatter_kernel<<<(unsigned)blocks, threads>>>(x, src, dst, out, n_edges);
}